// round 11
// baseline (speedup 1.0000x reference)
#include <cuda_runtime.h>

// Problem constants
#define B_ROWS 16
#define NCOL 2048
#define M 4096          // flat rows
#define D 8
#define NC 65536
#define ROWS_PER_M 256  // flat rows per batch row

// Argmin tunables: 8 rows/thread (4 packed row-pairs), codes walked scalar
#define ROWS_PER_THREAD 8
#define RP 4                                     // row-pairs
#define NWARPS 8
#define ROWS_PER_BLOCK (NWARPS * ROWS_PER_THREAD)  // 64
#define NSEG 32
#define SEG_CODES (NC / NSEG)                    // 2048
#define TILE 512                                 // codes per shared tile
#define NTILES (SEG_CODES / TILE)                // 4

typedef unsigned long long ull;

// Scratch
__device__ float g_scale[B_ROWS];
__device__ float g_planes[9][NC];    // dim-major planes (8 dims + norm)
__device__ ull   g_key[M];           // (monotone dist bits << 32) | tileId
__device__ int   g_idx[M];
__device__ float g_sums[NC * D];
__device__ float g_counts[NC];

__device__ __forceinline__ ull pack2(float lo, float hi) {
    ull r;
    asm("mov.b64 %0, {%1, %2};" : "=l"(r) : "f"(lo), "f"(hi));
    return r;
}
__device__ __forceinline__ void unpack2(ull v, float& lo, float& hi) {
    asm("mov.b64 {%0, %1}, %2;" : "=f"(lo), "=f"(hi) : "l"(v));
}
__device__ __forceinline__ void fma2(ull& d, ull a, ull b) {
    asm("fma.rn.f32x2 %0, %1, %2, %3;" : "=l"(d) : "l"(a), "l"(b), "l"(d));
}
__device__ __forceinline__ unsigned smem_u32(const void* p) {
    return (unsigned)__cvta_generic_to_shared(p);
}
__device__ __forceinline__ void cpa16(unsigned dst, const void* src) {
    asm volatile("cp.async.cg.shared.global [%0], [%1], 16;" :: "r"(dst), "l"(src));
}
__device__ __forceinline__ void cpa_commit() {
    asm volatile("cp.async.commit_group;");
}
template <int N>
__device__ __forceinline__ void cpa_wait() {
    asm volatile("cp.async.wait_group %0;" :: "n"(N));
}

// ---------------------------------------------------------------------------
// Fused prologue: zero sums/counts, init keys, build dim-major planes +
// norms, and (blocks 0..15) per-batch-row scale.
// ---------------------------------------------------------------------------
__global__ void k_pre(const float* __restrict__ x, const float* __restrict__ cb) {
    int t = blockIdx.x * blockDim.x + threadIdx.x;

    g_sums[t] = 0.f;                       // grid covers exactly NC*D
    if (t < NC) g_counts[t] = 0.f;
    if (t < M) g_key[t] = 0xFFFFFFFFFFFFFFFFull;

    if (t < NC) {                          // build planes for code t
        const float4* cbv = (const float4*)cb;
        float4 a = cbv[2 * t], b = cbv[2 * t + 1];
        g_planes[0][t] = a.x;
        g_planes[1][t] = a.y;
        g_planes[2][t] = a.z;
        g_planes[3][t] = a.w;
        g_planes[4][t] = b.x;
        g_planes[5][t] = b.y;
        g_planes[6][t] = b.z;
        g_planes[7][t] = b.w;
        g_planes[8][t] = a.x * a.x + a.y * a.y + a.z * a.z + a.w * a.w +
                         b.x * b.x + b.y * b.y + b.z * b.z + b.w * b.w;
    }

    if (blockIdx.x < B_ROWS) {
        __shared__ float sh[256];
        const float* row = x + blockIdx.x * NCOL;
        float s = 0.f;
        for (int i = threadIdx.x; i < NCOL; i += blockDim.x) s += fabsf(row[i]);
        sh[threadIdx.x] = s;
        __syncthreads();
        for (int off = 128; off > 0; off >>= 1) {
            if (threadIdx.x < off) sh[threadIdx.x] += sh[threadIdx.x + off];
            __syncthreads();
        }
        if (threadIdx.x == 0) g_scale[blockIdx.x] = sh[0] * (1.0f / NCOL);
    }
}

// ---------------------------------------------------------------------------
// Pass 1: per-row min distance + winning 512-code tile.
// Two ROWS ride the f32x2 lanes; codes walked scalar from dim-major shared
// planes. Double-buffered cp.async staging, one barrier per tile.
// ---------------------------------------------------------------------------
__global__ void __launch_bounds__(256, 2) k_argmin(const float* __restrict__ x) {
    __shared__ float shp[2][9][TILE];   // 36 KB

    int row0 = blockIdx.x * ROWS_PER_BLOCK;
    int segBase = blockIdx.y * SEG_CODES;
    int ct = threadIdx.x & 31;
    int w = threadIdx.x >> 5;
    int myrow0 = row0 + w * ROWS_PER_THREAD;
    int tid = threadIdx.x;

    // Queries: 4 row-pairs x 8 dims, packed (f_even[j], f_odd[j]) * (-2/scale)
    ull f2[RP][D];
#pragma unroll
    for (int rp = 0; rp < RP; rp++) {
        int m0 = myrow0 + 2 * rp;
        float s0 = -2.0f / g_scale[m0 / ROWS_PER_M];
        float s1 = -2.0f / g_scale[(m0 + 1) / ROWS_PER_M];
        const float4* x0 = (const float4*)(x + m0 * D);
        const float4* x1 = (const float4*)(x + (m0 + 1) * D);
        float4 a0 = x0[0], b0 = x0[1];
        float4 a1 = x1[0], b1 = x1[1];
        f2[rp][0] = pack2(a0.x * s0, a1.x * s1);
        f2[rp][1] = pack2(a0.y * s0, a1.y * s1);
        f2[rp][2] = pack2(a0.z * s0, a1.z * s1);
        f2[rp][3] = pack2(a0.w * s0, a1.w * s1);
        f2[rp][4] = pack2(b0.x * s0, b1.x * s1);
        f2[rp][5] = pack2(b0.y * s0, b1.y * s1);
        f2[rp][6] = pack2(b0.z * s0, b1.z * s1);
        f2[rp][7] = pack2(b0.w * s0, b1.w * s1);
    }

    float bestV[ROWS_PER_THREAD];
    int bestT[ROWS_PER_THREAD];
#pragma unroll
    for (int r = 0; r < ROWS_PER_THREAD; r++) { bestV[r] = 3.4e38f; bestT[r] = 0; }

    // Prologue: stage tile 0 (9 planes x 128 float4 = 1152 tasks)
#pragma unroll
    for (int q = tid; q < 9 * (TILE / 4); q += 256) {
        int j = q >> 7;
        int c4 = q & 127;
        cpa16(smem_u32(&shp[0][j][c4 * 4]), &g_planes[j][segBase + c4 * 4]);
    }
    cpa_commit();

    for (int t = 0; t < NTILES; t++) {
        int b = t & 1;
        cpa_wait<0>();        // tile t landed (only group in flight)
        __syncthreads();      // visibility + buffer b^1 released by compute t-1

        if (t + 1 < NTILES) {
            int base = segBase + (t + 1) * TILE;
#pragma unroll
            for (int q = tid; q < 9 * (TILE / 4); q += 256) {
                int j = q >> 7;
                int c4 = q & 127;
                cpa16(smem_u32(&shp[b ^ 1][j][c4 * 4]), &g_planes[j][base + c4 * 4]);
            }
            cpa_commit();
        }

        float pl[RP], ph[RP];
#pragma unroll
        for (int rp = 0; rp < RP; rp++) { pl[rp] = 3.4e38f; ph[rp] = 3.4e38f; }

#pragma unroll 4
        for (int i = 0; i < TILE / 32; i++) {
            int c = ct + 32 * i;
            float v0 = shp[b][0][c];
            float v1 = shp[b][1][c];
            float v2 = shp[b][2][c];
            float v3 = shp[b][3][c];
            float v4 = shp[b][4][c];
            float v5 = shp[b][5][c];
            float v6 = shp[b][6][c];
            float v7 = shp[b][7][c];
            float vn = shp[b][8][c];
            ull q0 = pack2(v0, v0);
            ull q1 = pack2(v1, v1);
            ull q2 = pack2(v2, v2);
            ull q3 = pack2(v3, v3);
            ull q4 = pack2(v4, v4);
            ull q5 = pack2(v5, v5);
            ull q6 = pack2(v6, v6);
            ull q7 = pack2(v7, v7);
            ull qn = pack2(vn, vn);
#pragma unroll
            for (int rp = 0; rp < RP; rp++) {
                ull d = qn;
                fma2(d, f2[rp][0], q0);
                fma2(d, f2[rp][1], q1);
                fma2(d, f2[rp][2], q2);
                fma2(d, f2[rp][3], q3);
                fma2(d, f2[rp][4], q4);
                fma2(d, f2[rp][5], q5);
                fma2(d, f2[rp][6], q6);
                fma2(d, f2[rp][7], q7);
                float de, dodd;
                unpack2(d, de, dodd);
                pl[rp] = fminf(pl[rp], de);
                ph[rp] = fminf(ph[rp], dodd);
            }
        }

        int tileId = (segBase >> 9) + t;
#pragma unroll
        for (int rp = 0; rp < RP; rp++) {
            if (pl[rp] < bestV[2 * rp]) { bestV[2 * rp] = pl[rp]; bestT[2 * rp] = tileId; }
            if (ph[rp] < bestV[2 * rp + 1]) { bestV[2 * rp + 1] = ph[rp]; bestT[2 * rp + 1] = tileId; }
        }
    }

    // Warp reduce lexicographic (val, tile) across the 32 code lanes
#pragma unroll
    for (int r = 0; r < ROWS_PER_THREAD; r++) {
        float d = bestV[r];
        int t = bestT[r];
        for (int off = 16; off > 0; off >>= 1) {
            float d2 = __shfl_down_sync(0xffffffffu, d, off);
            int t2 = __shfl_down_sync(0xffffffffu, t, off);
            if (d2 < d || (d2 == d && t2 < t)) { d = d2; t = t2; }
        }
        if (ct == 0) {
            unsigned int ud = __float_as_uint(d);
            ud = (ud & 0x80000000u) ? ~ud : (ud | 0x80000000u);
            ull key = ((ull)ud << 32) | (unsigned int)t;
            atomicMin(&g_key[myrow0 + r], key);
        }
    }
}

// ---------------------------------------------------------------------------
// Pass 2 (resolve + scatter): one warp per row does a SELF-CONTAINED
// (val, idx) lexicographic argmin over its winning 512-code tile — no float
// equality against the recorded min. Pass-1 and pass-2 use the identical
// scalar fma sequence (seed=norm, dims 0..7), so the winning tile contains
// the row's global min; within the tile, ascending scan + strict < gives
// jnp.argmin first-index semantics; cross-tile ties resolved by pass-1's
// lowest-tile key. Then the warp scatters count + dim-sums.
// ---------------------------------------------------------------------------
__global__ void __launch_bounds__(256) k_resolve(const float* __restrict__ x) {
    int m = blockIdx.x * 8 + (threadIdx.x >> 5);
    int lane = threadIdx.x & 31;

    int tile = (int)(g_key[m] & 0xFFFFFFFFu);
    int base = tile * TILE;

    float s = g_scale[m / ROWS_PER_M];
    float c0 = -2.0f / s;     // identical form to pass 1
    float inv = 1.0f / s;
    const float4* xr = (const float4*)(x + m * D);
    float4 a = xr[0], b = xr[1];
    float f0 = a.x * c0, f1 = a.y * c0, f2v = a.z * c0, f3 = a.w * c0;
    float f4 = b.x * c0, f5 = b.y * c0, f6 = b.z * c0, f7 = b.w * c0;

    float bv = 3.4e38f;
    int bi = base + lane;     // safe in-range default

#pragma unroll
    for (int p = 0; p < TILE / 32; p++) {
        int c = base + lane + 32 * p;   // ascending per lane
        float d = g_planes[8][c];
        d = fmaf(f0, g_planes[0][c], d);
        d = fmaf(f1, g_planes[1][c], d);
        d = fmaf(f2v, g_planes[2][c], d);
        d = fmaf(f3, g_planes[3][c], d);
        d = fmaf(f4, g_planes[4][c], d);
        d = fmaf(f5, g_planes[5][c], d);
        d = fmaf(f6, g_planes[6][c], d);
        d = fmaf(f7, g_planes[7][c], d);
        if (d < bv) { bv = d; bi = c; }   // strict <: first index per lane
    }

    // Butterfly lexicographic reduce so ALL lanes hold (bv, bi)
    for (int off = 16; off > 0; off >>= 1) {
        float d2 = __shfl_xor_sync(0xffffffffu, bv, off);
        int i2 = __shfl_xor_sync(0xffffffffu, bi, off);
        if (d2 < bv || (d2 == bv && i2 < bi)) { bv = d2; bi = i2; }
    }

    if (lane == 0) {
        g_idx[m] = bi;
        atomicAdd(&g_counts[bi], 1.f);
    }
    if (lane < D) {
        float v = x[m * D + lane] * inv;
        atomicAdd(&g_sums[bi * D + lane], v);
    }
}

// ---------------------------------------------------------------------------
__global__ void k_gather(float* __restrict__ out) {
    int t = blockIdx.x * blockDim.x + threadIdx.x;
    if (t >= M * D) return;
    int m = t >> 3;
    int j = t & 7;
    int idx = g_idx[m];
    float cnt = g_counts[idx];
    cnt = cnt < 1.f ? 1.f : cnt;
    out[t] = g_scale[m / ROWS_PER_M] * (g_sums[idx * D + j] / cnt);
}

// ---------------------------------------------------------------------------
extern "C" void kernel_launch(void* const* d_in, const int* in_sizes, int n_in,
                              void* d_out, int out_size) {
    const float* x = (const float*)d_in[0];
    const float* cb = (const float*)d_in[1];
    if (n_in >= 2 && in_sizes[0] > in_sizes[1]) {
        x = (const float*)d_in[1];
        cb = (const float*)d_in[0];
    }
    float* out = (float*)d_out;

    k_pre<<<(NC * D) / 256, 256>>>(x, cb);
    dim3 grid(M / ROWS_PER_BLOCK, NSEG);
    k_argmin<<<grid, 256>>>(x);
    k_resolve<<<M / 8, 256>>>(x);
    k_gather<<<(M * D) / 256, 256>>>(out);
}

// round 12
// speedup vs baseline: 1.1341x; 1.1341x over previous
#include <cuda_runtime.h>

// Problem constants
#define B_ROWS 16
#define NCOL 2048
#define M 4096          // flat rows
#define D 8
#define NC 65536
#define ROWS_PER_M 256  // flat rows per batch row

// Argmin tunables: 8 rows/thread (4 packed row-pairs), codes walked scalar
#define ROWS_PER_THREAD 8
#define RP 4                                     // row-pairs
#define NWARPS 8
#define ROWS_PER_BLOCK (NWARPS * ROWS_PER_THREAD)  // 64
#define NSEG 16
#define SEG_CODES (NC / NSEG)                    // 4096
#define TILE 1024                                // codes per shared tile
#define NTILES (SEG_CODES / TILE)                // 4
#define HALF (TILE / 2)                          // 512-code min-tracking unit

typedef unsigned long long ull;

// Scratch
__device__ float g_scale[B_ROWS];
__device__ float g_planes[9][NC];    // dim-major planes (8 dims + norm)
__device__ ull   g_key[M];           // (monotone dist bits << 32) | tileId(512)
__device__ int   g_idx[M];
__device__ float g_sums[NC * D];
__device__ float g_counts[NC];

__device__ __forceinline__ ull pack2(float lo, float hi) {
    ull r;
    asm("mov.b64 %0, {%1, %2};" : "=l"(r) : "f"(lo), "f"(hi));
    return r;
}
__device__ __forceinline__ void unpack2(ull v, float& lo, float& hi) {
    asm("mov.b64 {%0, %1}, %2;" : "=f"(lo), "=f"(hi) : "l"(v));
}
__device__ __forceinline__ void fma2(ull& d, ull a, ull b) {
    asm("fma.rn.f32x2 %0, %1, %2, %3;" : "=l"(d) : "l"(a), "l"(b), "l"(d));
}
__device__ __forceinline__ unsigned smem_u32(const void* p) {
    return (unsigned)__cvta_generic_to_shared(p);
}
__device__ __forceinline__ void cpa16(unsigned dst, const void* src) {
    asm volatile("cp.async.cg.shared.global [%0], [%1], 16;" :: "r"(dst), "l"(src));
}
__device__ __forceinline__ void cpa_commit() {
    asm volatile("cp.async.commit_group;");
}
template <int N>
__device__ __forceinline__ void cpa_wait() {
    asm volatile("cp.async.wait_group %0;" :: "n"(N));
}

// ---------------------------------------------------------------------------
// Fused prologue: zero sums/counts, init keys, build dim-major planes +
// norms, and (blocks 0..15) per-batch-row scale.
// ---------------------------------------------------------------------------
__global__ void k_pre(const float* __restrict__ x, const float* __restrict__ cb) {
    int t = blockIdx.x * blockDim.x + threadIdx.x;

    g_sums[t] = 0.f;                       // grid covers exactly NC*D
    if (t < NC) g_counts[t] = 0.f;
    if (t < M) g_key[t] = 0xFFFFFFFFFFFFFFFFull;

    if (t < NC) {                          // build planes for code t
        const float4* cbv = (const float4*)cb;
        float4 a = cbv[2 * t], b = cbv[2 * t + 1];
        g_planes[0][t] = a.x;
        g_planes[1][t] = a.y;
        g_planes[2][t] = a.z;
        g_planes[3][t] = a.w;
        g_planes[4][t] = b.x;
        g_planes[5][t] = b.y;
        g_planes[6][t] = b.z;
        g_planes[7][t] = b.w;
        g_planes[8][t] = a.x * a.x + a.y * a.y + a.z * a.z + a.w * a.w +
                         b.x * b.x + b.y * b.y + b.z * b.z + b.w * b.w;
    }

    if (blockIdx.x < B_ROWS) {
        __shared__ float sh[256];
        const float* row = x + blockIdx.x * NCOL;
        float s = 0.f;
        for (int i = threadIdx.x; i < NCOL; i += blockDim.x) s += fabsf(row[i]);
        sh[threadIdx.x] = s;
        __syncthreads();
        for (int off = 128; off > 0; off >>= 1) {
            if (threadIdx.x < off) sh[threadIdx.x] += sh[threadIdx.x + off];
            __syncthreads();
        }
        if (threadIdx.x == 0) g_scale[blockIdx.x] = sh[0] * (1.0f / NCOL);
    }
}

// ---------------------------------------------------------------------------
// Pass 1: per-row min distance + winning 512-code half-tile.
// Two ROWS ride the f32x2 lanes; codes walked scalar from dim-major shared
// planes. 1024-code staging tiles (4 barriers/segment), min tracked per
// 512-code half. Double-buffered cp.async, one barrier per tile.
// ---------------------------------------------------------------------------
__global__ void __launch_bounds__(256, 2) k_argmin(const float* __restrict__ x) {
    __shared__ float shp[2][9][TILE];   // 72 KB

    int row0 = blockIdx.x * ROWS_PER_BLOCK;
    int segBase = blockIdx.y * SEG_CODES;
    int ct = threadIdx.x & 31;
    int w = threadIdx.x >> 5;
    int myrow0 = row0 + w * ROWS_PER_THREAD;
    int tid = threadIdx.x;

    // Queries: 4 row-pairs x 8 dims, packed (f_even[j], f_odd[j]) * (-2/scale)
    ull f2[RP][D];
#pragma unroll
    for (int rp = 0; rp < RP; rp++) {
        int m0 = myrow0 + 2 * rp;
        float s0 = -2.0f / g_scale[m0 / ROWS_PER_M];
        float s1 = -2.0f / g_scale[(m0 + 1) / ROWS_PER_M];
        const float4* x0 = (const float4*)(x + m0 * D);
        const float4* x1 = (const float4*)(x + (m0 + 1) * D);
        float4 a0 = x0[0], b0 = x0[1];
        float4 a1 = x1[0], b1 = x1[1];
        f2[rp][0] = pack2(a0.x * s0, a1.x * s1);
        f2[rp][1] = pack2(a0.y * s0, a1.y * s1);
        f2[rp][2] = pack2(a0.z * s0, a1.z * s1);
        f2[rp][3] = pack2(a0.w * s0, a1.w * s1);
        f2[rp][4] = pack2(b0.x * s0, b1.x * s1);
        f2[rp][5] = pack2(b0.y * s0, b1.y * s1);
        f2[rp][6] = pack2(b0.z * s0, b1.z * s1);
        f2[rp][7] = pack2(b0.w * s0, b1.w * s1);
    }

    float bestV[ROWS_PER_THREAD];
    int bestT[ROWS_PER_THREAD];
#pragma unroll
    for (int r = 0; r < ROWS_PER_THREAD; r++) { bestV[r] = 3.4e38f; bestT[r] = 0; }

    // Prologue: stage tile 0 (9 planes x 256 float4 = 2304 tasks)
#pragma unroll
    for (int q = tid; q < 9 * (TILE / 4); q += 256) {
        int j = q >> 8;
        int c4 = q & 255;
        cpa16(smem_u32(&shp[0][j][c4 * 4]), &g_planes[j][segBase + c4 * 4]);
    }
    cpa_commit();

    for (int t = 0; t < NTILES; t++) {
        int b = t & 1;
        cpa_wait<0>();        // tile t landed (only group in flight)
        __syncthreads();      // visibility + buffer b^1 released by compute t-1

        if (t + 1 < NTILES) {
            int base = segBase + (t + 1) * TILE;
#pragma unroll
            for (int q = tid; q < 9 * (TILE / 4); q += 256) {
                int j = q >> 8;
                int c4 = q & 255;
                cpa16(smem_u32(&shp[b ^ 1][j][c4 * 4]), &g_planes[j][base + c4 * 4]);
            }
            cpa_commit();
        }

        // Two 512-code halves, each with its own min accumulators + tileId
#pragma unroll
        for (int h = 0; h < 2; h++) {
            float pl[RP], ph[RP];
#pragma unroll
            for (int rp = 0; rp < RP; rp++) { pl[rp] = 3.4e38f; ph[rp] = 3.4e38f; }

#pragma unroll 8
            for (int i = 0; i < HALF / 32; i++) {
                int c = h * HALF + ct + 32 * i;
                float v0 = shp[b][0][c];
                float v1 = shp[b][1][c];
                float v2 = shp[b][2][c];
                float v3 = shp[b][3][c];
                float v4 = shp[b][4][c];
                float v5 = shp[b][5][c];
                float v6 = shp[b][6][c];
                float v7 = shp[b][7][c];
                float vn = shp[b][8][c];
                ull q0 = pack2(v0, v0);
                ull q1 = pack2(v1, v1);
                ull q2 = pack2(v2, v2);
                ull q3 = pack2(v3, v3);
                ull q4 = pack2(v4, v4);
                ull q5 = pack2(v5, v5);
                ull q6 = pack2(v6, v6);
                ull q7 = pack2(v7, v7);
                ull qn = pack2(vn, vn);
#pragma unroll
                for (int rp = 0; rp < RP; rp++) {
                    ull d = qn;
                    fma2(d, f2[rp][0], q0);
                    fma2(d, f2[rp][1], q1);
                    fma2(d, f2[rp][2], q2);
                    fma2(d, f2[rp][3], q3);
                    fma2(d, f2[rp][4], q4);
                    fma2(d, f2[rp][5], q5);
                    fma2(d, f2[rp][6], q6);
                    fma2(d, f2[rp][7], q7);
                    float de, dodd;
                    unpack2(d, de, dodd);
                    pl[rp] = fminf(pl[rp], de);
                    ph[rp] = fminf(ph[rp], dodd);
                }
            }

            int tileId = ((segBase + t * TILE) >> 9) + h;   // 512-code units
#pragma unroll
            for (int rp = 0; rp < RP; rp++) {
                if (pl[rp] < bestV[2 * rp]) { bestV[2 * rp] = pl[rp]; bestT[2 * rp] = tileId; }
                if (ph[rp] < bestV[2 * rp + 1]) { bestV[2 * rp + 1] = ph[rp]; bestT[2 * rp + 1] = tileId; }
            }
        }
    }

    // Warp reduce lexicographic (val, tile) across the 32 code lanes
#pragma unroll
    for (int r = 0; r < ROWS_PER_THREAD; r++) {
        float d = bestV[r];
        int t = bestT[r];
        for (int off = 16; off > 0; off >>= 1) {
            float d2 = __shfl_down_sync(0xffffffffu, d, off);
            int t2 = __shfl_down_sync(0xffffffffu, t, off);
            if (d2 < d || (d2 == d && t2 < t)) { d = d2; t = t2; }
        }
        if (ct == 0) {
            unsigned int ud = __float_as_uint(d);
            ud = (ud & 0x80000000u) ? ~ud : (ud | 0x80000000u);
            ull key = ((ull)ud << 32) | (unsigned int)t;
            atomicMin(&g_key[myrow0 + r], key);
        }
    }
}

// ---------------------------------------------------------------------------
// Pass 2 (resolve + scatter): one warp per row does a SELF-CONTAINED
// (val, idx) lexicographic argmin over its winning 512-code half-tile.
// Pass-1/pass-2 use the identical scalar fma sequence, so the winning tile
// contains the row's global min; ascending in-tile scan + strict < gives
// jnp.argmin first-index semantics; cross-tile ties resolved by pass-1's
// lowest-tile key. Then the warp scatters count + dim-sums.
// ---------------------------------------------------------------------------
__global__ void __launch_bounds__(256) k_resolve(const float* __restrict__ x) {
    int m = blockIdx.x * 8 + (threadIdx.x >> 5);
    int lane = threadIdx.x & 31;

    int tile = (int)(g_key[m] & 0xFFFFFFFFu);
    int base = tile * 512;

    float s = g_scale[m / ROWS_PER_M];
    float c0 = -2.0f / s;     // identical form to pass 1
    float inv = 1.0f / s;
    const float4* xr = (const float4*)(x + m * D);
    float4 a = xr[0], b = xr[1];
    float f0 = a.x * c0, f1 = a.y * c0, f2v = a.z * c0, f3 = a.w * c0;
    float f4 = b.x * c0, f5 = b.y * c0, f6 = b.z * c0, f7 = b.w * c0;

    float bv = 3.4e38f;
    int bi = base + lane;

#pragma unroll
    for (int p = 0; p < 512 / 32; p++) {
        int c = base + lane + 32 * p;   // ascending per lane
        float d = g_planes[8][c];
        d = fmaf(f0, g_planes[0][c], d);
        d = fmaf(f1, g_planes[1][c], d);
        d = fmaf(f2v, g_planes[2][c], d);
        d = fmaf(f3, g_planes[3][c], d);
        d = fmaf(f4, g_planes[4][c], d);
        d = fmaf(f5, g_planes[5][c], d);
        d = fmaf(f6, g_planes[6][c], d);
        d = fmaf(f7, g_planes[7][c], d);
        if (d < bv) { bv = d; bi = c; }   // strict <: first index per lane
    }

    // Butterfly lexicographic reduce so ALL lanes hold (bv, bi)
    for (int off = 16; off > 0; off >>= 1) {
        float d2 = __shfl_xor_sync(0xffffffffu, bv, off);
        int i2 = __shfl_xor_sync(0xffffffffu, bi, off);
        if (d2 < bv || (d2 == bv && i2 < bi)) { bv = d2; bi = i2; }
    }

    if (lane == 0) {
        g_idx[m] = bi;
        atomicAdd(&g_counts[bi], 1.f);
    }
    if (lane < D) {
        float v = x[m * D + lane] * inv;
        atomicAdd(&g_sums[bi * D + lane], v);
    }
}

// ---------------------------------------------------------------------------
__global__ void k_gather(float* __restrict__ out) {
    int t = blockIdx.x * blockDim.x + threadIdx.x;
    if (t >= M * D) return;
    int m = t >> 3;
    int j = t & 7;
    int idx = g_idx[m];
    float cnt = g_counts[idx];
    cnt = cnt < 1.f ? 1.f : cnt;
    out[t] = g_scale[m / ROWS_PER_M] * (g_sums[idx * D + j] / cnt);
}

// ---------------------------------------------------------------------------
extern "C" void kernel_launch(void* const* d_in, const int* in_sizes, int n_in,
                              void* d_out, int out_size) {
    const float* x = (const float*)d_in[0];
    const float* cb = (const float*)d_in[1];
    if (n_in >= 2 && in_sizes[0] > in_sizes[1]) {
        x = (const float*)d_in[1];
        cb = (const float*)d_in[0];
    }
    float* out = (float*)d_out;

    k_pre<<<(NC * D) / 256, 256>>>(x, cb);
    dim3 grid(M / ROWS_PER_BLOCK, NSEG);
    k_argmin<<<grid, 256>>>(x);
    k_resolve<<<M / 8, 256>>>(x);
    k_gather<<<(M * D) / 256, 256>>>(out);
}